// round 6
// baseline (speedup 1.0000x reference)
#include <cuda_runtime.h>
#include <cuda_bf16.h>

#define NN 16500
#define NE 100000
#define KT 3
#define GEN_EPS 1e-7f
#define BN_EPS 1e-5f

// ---------------- scratch ----------------
__device__ int   d_cnt[KT][NN];
__device__ int   d_off[KT][NN + 1];
__device__ int   d_cur[KT][NN];
__device__ int   d_eid[KT][NE];
__device__ float d_agg[NN * 256];
__device__ float d_h[NN * 512];
__device__ float d_acc[NN * 256];
__device__ float d_xcur[NN * 256];
__device__ float d_cs[512], d_css[512], d_scale[512], d_shift[512];

// ---------------- CSR build ----------------
__global__ void k_zero_counts() {
    int i = blockIdx.x * blockDim.x + threadIdx.x;
    if (i < KT * NN) ((int*)d_cnt)[i] = 0;
}

__global__ void k_count(const int* __restrict__ ei) {
    int i = blockIdx.x * blockDim.x + threadIdx.x;
    if (i >= KT * NE) return;
    int k = i / NE, e = i % NE;
    int dst = ei[k * 2 * NE + NE + e];
    atomicAdd(&d_cnt[k][dst], 1);
}

__global__ void k_scan() {  // blockIdx.x = type
    __shared__ int sh[1024];
    int k = blockIdx.x, tid = threadIdx.x;
    int carry = 0;
    if (tid == 0) d_off[k][0] = 0;
    for (int base = 0; base < NN; base += 1024) {
        int i = base + tid;
        int v = (i < NN) ? d_cnt[k][i] : 0;
        sh[tid] = v;
        __syncthreads();
        for (int o = 1; o < 1024; o <<= 1) {
            int t = (tid >= o) ? sh[tid - o] : 0;
            __syncthreads();
            sh[tid] += t;
            __syncthreads();
        }
        int inc = sh[tid];
        int tot = sh[1023];
        if (i < NN) {
            d_off[k][i + 1] = carry + inc;
            d_cur[k][i]     = carry + inc - v;
        }
        __syncthreads();
        carry += tot;
    }
}

__global__ void k_fill(const int* __restrict__ ei) {
    int i = blockIdx.x * blockDim.x + threadIdx.x;
    if (i >= KT * NE) return;
    int k = i / NE, e = i % NE;
    int dst = ei[k * 2 * NE + NE + e];
    int pos = atomicAdd(&d_cur[k][dst], 1);
    d_eid[k][pos] = e;
}

// ---------------- GENConv aggregation (online segment softmax) ----------------
__global__ void k_aggr(const float* __restrict__ xin,
                       const int* __restrict__ ei,
                       const float* __restrict__ ea,
                       const float* __restrict__ We,
                       const float* __restrict__ be,
                       float* __restrict__ agg,
                       int ci, int k) {
    int n = blockIdx.x;
    int c = threadIdx.x;
    if (c >= ci) return;
    const int*   src = ei + k * 2 * NE;
    const float* eak = ea + k * NE;
    float we = We[c], bec = be[c];
    float xn = xin[n * ci + c];
    float v = fmaxf(xn + we + bec, 0.f) + GEN_EPS;  // self loop (ea = 1)
    float m = v, den = 1.f, ws = v;
    int j0 = d_off[k][n], j1 = d_off[k][n + 1];
    for (int j = j0; j < j1; j++) {
        int e = d_eid[k][j];
        int s = src[e];
        float a = eak[e];
        float u = fmaxf(xin[s * ci + c] + a * we + bec, 0.f) + GEN_EPS;
        float nm = fmaxf(m, u);
        float sa = __expf(m - nm);
        float sb = __expf(u - nm);
        den = den * sa + sb;
        ws  = ws * sa + u * sb;
        m = nm;
    }
    agg[n * ci + c] = ws / den + xn;
}

// ---------------- fp32 tiled GEMM: C = A @ B + bias (+C if beta) ----------------
#define BM 128
#define BN 128
#define BK 8
__global__ __launch_bounds__(256) void k_gemm(
    const float* __restrict__ A, const float* __restrict__ B,
    const float* __restrict__ bias, float* __restrict__ C,
    int M, int Kd, int Nd, int beta) {
    __shared__ float As[BK][BM];
    __shared__ float Bs[BK][BN];
    int tid = threadIdx.x;
    int tx = tid & 15, ty = tid >> 4;
    int row0 = blockIdx.y * BM;
    int col0 = blockIdx.x * BN;

    float acc[8][8];
#pragma unroll
    for (int i = 0; i < 8; i++)
#pragma unroll
        for (int j = 0; j < 8; j++) acc[i][j] = 0.f;

    int arow = row0 + (tid >> 1);
    int akq  = (tid & 1) << 2;
    int brow = tid >> 5;
    int bcol = (tid & 31) << 2;

    for (int kt = 0; kt < Kd; kt += BK) {
#pragma unroll
        for (int j = 0; j < 4; j++) {
            float v = 0.f;
            if (arow < M && (kt + akq + j) < Kd) v = A[(long)arow * Kd + kt + akq + j];
            As[akq + j][tid >> 1] = v;
        }
        {
            int gk = kt + brow;
            int gn = col0 + bcol;
            float t[4] = {0.f, 0.f, 0.f, 0.f};
            if (gk < Kd) {
#pragma unroll
                for (int e = 0; e < 4; e++)
                    if (gn + e < Nd) t[e] = B[(long)gk * Nd + gn + e];
            }
            Bs[brow][bcol + 0] = t[0];
            Bs[brow][bcol + 1] = t[1];
            Bs[brow][bcol + 2] = t[2];
            Bs[brow][bcol + 3] = t[3];
        }
        __syncthreads();
#pragma unroll
        for (int kk = 0; kk < BK; kk++) {
            float a[8], b[8];
#pragma unroll
            for (int i = 0; i < 8; i++) a[i] = As[kk][ty + i * 16];
#pragma unroll
            for (int j = 0; j < 8; j++) b[j] = Bs[kk][tx + j * 16];
#pragma unroll
            for (int i = 0; i < 8; i++)
#pragma unroll
                for (int j = 0; j < 8; j++) acc[i][j] = fmaf(a[i], b[j], acc[i][j]);
        }
        __syncthreads();
    }

#pragma unroll
    for (int i = 0; i < 8; i++) {
        int r = row0 + ty + i * 16;
        if (r >= M) continue;
#pragma unroll
        for (int j = 0; j < 8; j++) {
            int c = col0 + tx + j * 16;
            if (c >= Nd) continue;
            float v = acc[i][j] + bias[c];
            long idx = (long)r * Nd + c;
            if (beta) v += C[idx];
            C[idx] = v;
        }
    }
}

// ---------------- BatchNorm (train stats) ----------------
__global__ void k_zero_stats(int C) {
    int i = threadIdx.x;
    if (i < C) { d_cs[i] = 0.f; d_css[i] = 0.f; }
}

__global__ void k_colstats(int C) {
    int r0 = blockIdx.x * 128;
    int rend = min(r0 + 128, NN);
    for (int cc = threadIdx.x; cc < C; cc += blockDim.x) {
        float s = 0.f, q = 0.f;
        for (int r = r0; r < rend; r++) {
            float v = d_h[(long)r * C + cc];
            s += v;
            q += v * v;
        }
        atomicAdd(&d_cs[cc], s);
        atomicAdd(&d_css[cc], q);
    }
}

__global__ void k_bnfinal(int C, const float* __restrict__ g,
                          const float* __restrict__ bt) {
    int c = threadIdx.x;
    if (c >= C) return;
    float mu  = d_cs[c] / (float)NN;
    float var = d_css[c] / (float)NN - mu * mu;
    var = fmaxf(var, 0.f);
    float s = g[c] * rsqrtf(var + BN_EPS);
    d_scale[c] = s;
    d_shift[c] = bt[c] - mu * s;
}

__global__ void k_bnapply(int C) {
    long i = (long)blockIdx.x * blockDim.x + threadIdx.x;
    long total = (long)NN * C;
    if (i >= total) return;
    int c = (int)(i % C);
    float v = d_h[i];
    d_h[i] = fmaxf(fmaf(v, d_scale[c], d_shift[c]), 0.f);
}

__global__ void k_leaky() {
    int i = blockIdx.x * blockDim.x + threadIdx.x;
    if (i >= NN * 256) return;
    float v = d_acc[i];
    d_xcur[i] = (v > 0.f) ? v : 0.01f * v;
}

// ---------------- launch ----------------
extern "C" void kernel_launch(void* const* d_in, const int* in_sizes, int n_in,
                              void* d_out, int out_size) {
    // CRITICAL: __device__ globals referenced from HOST code give the host
    // shadow address (silently GPU-readable on GB300 via ATS!). Resolve the
    // REAL device addresses. cudaGetSymbolAddress is a pure query: no alloc,
    // no sync, capture-safe.
    float *p_agg, *p_h, *p_acc, *p_xcur;
    cudaGetSymbolAddress((void**)&p_agg,  d_agg);
    cudaGetSymbolAddress((void**)&p_h,    d_h);
    cudaGetSymbolAddress((void**)&p_acc,  d_acc);
    cudaGetSymbolAddress((void**)&p_xcur, d_xcur);

    const float* x  = (const float*)d_in[0];
    const int*   ei = (const int*)d_in[1];
    const float* ea = (const float*)d_in[2];

    const int ciL[3] = {170, 256, 256};
    const int chL[3] = {340, 512, 512};
    const int co = 256;

    // build CSR (edge lists identical across layers)
    k_zero_counts<<<(KT * NN + 255) / 256, 256>>>();
    k_count<<<(KT * NE + 255) / 256, 256>>>(ei);
    k_scan<<<KT, 1024>>>();
    k_fill<<<(KT * NE + 255) / 256, 256>>>(ei);

    const float* xin = x;
    for (int l = 0; l < 3; l++) {
        int ci = ciL[l], ch = chL[l];
        const float* We = (const float*)d_in[3 + l * 8 + 0];
        const float* be = (const float*)d_in[3 + l * 8 + 1];
        const float* Wa = (const float*)d_in[3 + l * 8 + 2];
        const float* ba = (const float*)d_in[3 + l * 8 + 3];
        const float* g  = (const float*)d_in[3 + l * 8 + 4];
        const float* bt = (const float*)d_in[3 + l * 8 + 5];
        const float* Wb = (const float*)d_in[3 + l * 8 + 6];
        const float* bb = (const float*)d_in[3 + l * 8 + 7];
        float* dest = (l == 2) ? (float*)d_out : p_acc;

        for (int k = 0; k < KT; k++) {
            k_aggr<<<NN, 256>>>(xin, ei, ea, We + k * ci, be + k * ci,
                                p_agg, ci, k);

            dim3 g1((ch + BN - 1) / BN, (NN + BM - 1) / BM);
            k_gemm<<<g1, 256>>>(p_agg, Wa + (long)k * ci * ch, ba + k * ch,
                                p_h, NN, ci, ch, 0);

            k_zero_stats<<<1, 512>>>(ch);
            k_colstats<<<(NN + 127) / 128, 256>>>(ch);
            k_bnfinal<<<1, 512>>>(ch, g + k * ch, bt + k * ch);
            long tot = (long)NN * ch;
            k_bnapply<<<(int)((tot + 255) / 256), 256>>>(ch);

            dim3 g2((co + BN - 1) / BN, (NN + BM - 1) / BM);
            k_gemm<<<g2, 256>>>(p_h, Wb + (long)k * ch * co, bb + k * co,
                                dest, NN, ch, co, (k > 0) ? 1 : 0);
        }
        if (l < 2) {
            k_leaky<<<(NN * 256 + 255) / 256, 256>>>();
            xin = p_xcur;
        }
    }
}

// round 7
// speedup vs baseline: 1.1256x; 1.1256x over previous
#include <cuda_runtime.h>
#include <cuda_bf16.h>

#define NN 16500
#define NE 100000
#define KT 3
#define GEN_EPS 1e-7f
#define BN_EPS 1e-5f

// ---------------- scratch ----------------
__device__ int   d_cnt[KT][NN];
__device__ int   d_off[KT][NN + 1];
__device__ int   d_cur[KT][NN];
__device__ int   d_eid[KT][NE];
__device__ float d_agg[KT][NN * 256];    // per-type aggregation output
__device__ float d_hh[KT][NN * 512];     // per-type hidden (pre-BN)
__device__ float d_accb[NN * 256];       // sum over types (layers 0,1)
__device__ float d_xcur[NN * 256];       // activations between layers
__device__ float d_cs[KT * 512], d_css[KT * 512];
__device__ float d_scale[KT * 512], d_shift[KT * 512];

// ---------------- CSR build ----------------
__global__ void k_zero_counts() {
    int i = blockIdx.x * blockDim.x + threadIdx.x;
    if (i < KT * NN) ((int*)d_cnt)[i] = 0;
}

__global__ void k_count(const int* __restrict__ ei) {
    int i = blockIdx.x * blockDim.x + threadIdx.x;
    if (i >= KT * NE) return;
    int k = i / NE, e = i % NE;
    atomicAdd(&d_cnt[k][ei[k * 2 * NE + NE + e]], 1);
}

__global__ void k_scan() {
    __shared__ int sh[1024];
    int k = blockIdx.x, tid = threadIdx.x;
    int carry = 0;
    if (tid == 0) d_off[k][0] = 0;
    for (int base = 0; base < NN; base += 1024) {
        int i = base + tid;
        int v = (i < NN) ? d_cnt[k][i] : 0;
        sh[tid] = v;
        __syncthreads();
        for (int o = 1; o < 1024; o <<= 1) {
            int t = (tid >= o) ? sh[tid - o] : 0;
            __syncthreads();
            sh[tid] += t;
            __syncthreads();
        }
        int inc = sh[tid];
        int tot = sh[1023];
        if (i < NN) {
            d_off[k][i + 1] = carry + inc;
            d_cur[k][i]     = carry + inc - v;
        }
        __syncthreads();
        carry += tot;
    }
}

__global__ void k_fill(const int* __restrict__ ei) {
    int i = blockIdx.x * blockDim.x + threadIdx.x;
    if (i >= KT * NE) return;
    int k = i / NE, e = i % NE;
    int pos = atomicAdd(&d_cur[k][ei[k * 2 * NE + NE + e]], 1);
    d_eid[k][pos] = e;
}

// ------------- batched GENConv aggregation (online segment softmax) ----------
__global__ void k_aggr(const float* __restrict__ xin,
                       const int* __restrict__ ei,
                       const float* __restrict__ ea,
                       const float* __restrict__ WeB,
                       const float* __restrict__ beB,
                       int ci) {
    int n = blockIdx.x;
    int k = blockIdx.y;
    int c = threadIdx.x;
    if (c >= ci) return;
    const int*   src = ei + k * 2 * NE;
    const float* eak = ea + k * NE;
    float we = WeB[k * ci + c], bec = beB[k * ci + c];
    float xn = xin[n * ci + c];
    float v = fmaxf(xn + we + bec, 0.f) + GEN_EPS;  // self loop (ea = 1)
    float m = v, den = 1.f, ws = v;
    int j0 = d_off[k][n], j1 = d_off[k][n + 1];
    for (int j = j0; j < j1; j++) {
        int e = d_eid[k][j];
        int s = src[e];
        float a = eak[e];
        float u = fmaxf(xin[s * ci + c] + a * we + bec, 0.f) + GEN_EPS;
        float nm = fmaxf(m, u);
        float sa = __expf(m - nm);
        float sb = __expf(u - nm);
        den = den * sa + sb;
        ws  = ws * sa + u * sb;
        m = nm;
    }
    d_agg[k][n * ci + c] = ws / den + xn;
}

// ---- GEMM1: h[z] = agg[z] @ Wa[z] + ba[z]; fused column sum/sumsq stats ----
#define BM 128
#define BN 128
#define BK 8
__global__ __launch_bounds__(256) void k_gemm1(
    const float* __restrict__ Wa, const float* __restrict__ ba,
    int M, int Kd, int Nd) {
    __shared__ float As[BK][BM];
    __shared__ float Bs[BK][BN];
    __shared__ float sSum[BN], sSsq[BN];
    int z = blockIdx.z;
    const float* A = d_agg[z];
    const float* B = Wa + (long)z * Kd * Nd;
    const float* bias = ba + z * Nd;
    float* C = d_hh[z];

    int tid = threadIdx.x;
    int tx = tid & 15, ty = tid >> 4;
    int row0 = blockIdx.y * BM;
    int col0 = blockIdx.x * BN;

    float acc[8][8];
#pragma unroll
    for (int i = 0; i < 8; i++)
#pragma unroll
        for (int j = 0; j < 8; j++) acc[i][j] = 0.f;

    int arow = row0 + (tid >> 1);
    int akq  = (tid & 1) << 2;
    int brow = tid >> 5;
    int bcol = (tid & 31) << 2;

    for (int kt = 0; kt < Kd; kt += BK) {
#pragma unroll
        for (int j = 0; j < 4; j++) {
            float v = 0.f;
            if (arow < M && (kt + akq + j) < Kd) v = A[(long)arow * Kd + kt + akq + j];
            As[akq + j][tid >> 1] = v;
        }
        {
            int gk = kt + brow;
            int gn = col0 + bcol;
            float t[4] = {0.f, 0.f, 0.f, 0.f};
            if (gk < Kd) {
#pragma unroll
                for (int e = 0; e < 4; e++)
                    if (gn + e < Nd) t[e] = B[(long)gk * Nd + gn + e];
            }
            Bs[brow][bcol + 0] = t[0];
            Bs[brow][bcol + 1] = t[1];
            Bs[brow][bcol + 2] = t[2];
            Bs[brow][bcol + 3] = t[3];
        }
        __syncthreads();
#pragma unroll
        for (int kk = 0; kk < BK; kk++) {
            float a[8], b[8];
#pragma unroll
            for (int i = 0; i < 8; i++) a[i] = As[kk][ty + i * 16];
#pragma unroll
            for (int j = 0; j < 8; j++) b[j] = Bs[kk][tx + j * 16];
#pragma unroll
            for (int i = 0; i < 8; i++)
#pragma unroll
                for (int j = 0; j < 8; j++) acc[i][j] = fmaf(a[i], b[j], acc[i][j]);
        }
        __syncthreads();
    }

    if (tid < BN) { sSum[tid] = 0.f; sSsq[tid] = 0.f; }
    __syncthreads();

    float colS[8], colQ[8];
#pragma unroll
    for (int j = 0; j < 8; j++) { colS[j] = 0.f; colQ[j] = 0.f; }
#pragma unroll
    for (int i = 0; i < 8; i++) {
        int r = row0 + ty + i * 16;
        if (r >= M) continue;
#pragma unroll
        for (int j = 0; j < 8; j++) {
            int c = col0 + tx + j * 16;
            if (c >= Nd) continue;
            float v = acc[i][j] + bias[c];
            C[(long)r * Nd + c] = v;
            colS[j] += v;
            colQ[j] += v * v;
        }
    }
#pragma unroll
    for (int j = 0; j < 8; j++) {
        atomicAdd(&sSum[tx + j * 16], colS[j]);
        atomicAdd(&sSsq[tx + j * 16], colQ[j]);
    }
    __syncthreads();
    if (tid < BN) {
        int c = col0 + tid;
        if (c < Nd) {
            atomicAdd(&d_cs[z * 512 + c], sSum[tid]);
            atomicAdd(&d_css[z * 512 + c], sSsq[tid]);
        }
    }
}

// ---- GEMM2: dest += relu(BN(h[z])) @ Wb[z]  (atomic accumulate over z) ----
__global__ __launch_bounds__(256) void k_gemm2(
    const float* __restrict__ Wb, float* __restrict__ C,
    int M, int Kd, int Nd) {
    __shared__ float As[BK][BM];
    __shared__ float Bs[BK][BN];
    int z = blockIdx.z;
    const float* A = d_hh[z];
    const float* B = Wb + (long)z * Kd * Nd;
    const float* sc = &d_scale[z * 512];
    const float* sh = &d_shift[z * 512];

    int tid = threadIdx.x;
    int tx = tid & 15, ty = tid >> 4;
    int row0 = blockIdx.y * BM;
    int col0 = blockIdx.x * BN;

    float acc[8][8];
#pragma unroll
    for (int i = 0; i < 8; i++)
#pragma unroll
        for (int j = 0; j < 8; j++) acc[i][j] = 0.f;

    int arow = row0 + (tid >> 1);
    int akq  = (tid & 1) << 2;
    int brow = tid >> 5;
    int bcol = (tid & 31) << 2;

    for (int kt = 0; kt < Kd; kt += BK) {
#pragma unroll
        for (int j = 0; j < 4; j++) {
            float v = 0.f;
            int ck = kt + akq + j;
            if (arow < M && ck < Kd) {
                v = A[(long)arow * Kd + ck];
                v = fmaxf(fmaf(v, sc[ck], sh[ck]), 0.f);   // fused BN + ReLU
            }
            As[akq + j][tid >> 1] = v;
        }
        {
            int gk = kt + brow;
            int gn = col0 + bcol;
            float t[4] = {0.f, 0.f, 0.f, 0.f};
            if (gk < Kd) {
#pragma unroll
                for (int e = 0; e < 4; e++)
                    if (gn + e < Nd) t[e] = B[(long)gk * Nd + gn + e];
            }
            Bs[brow][bcol + 0] = t[0];
            Bs[brow][bcol + 1] = t[1];
            Bs[brow][bcol + 2] = t[2];
            Bs[brow][bcol + 3] = t[3];
        }
        __syncthreads();
#pragma unroll
        for (int kk = 0; kk < BK; kk++) {
            float a[8], b[8];
#pragma unroll
            for (int i = 0; i < 8; i++) a[i] = As[kk][ty + i * 16];
#pragma unroll
            for (int j = 0; j < 8; j++) b[j] = Bs[kk][tx + j * 16];
#pragma unroll
            for (int i = 0; i < 8; i++)
#pragma unroll
                for (int j = 0; j < 8; j++) acc[i][j] = fmaf(a[i], b[j], acc[i][j]);
        }
        __syncthreads();
    }

#pragma unroll
    for (int i = 0; i < 8; i++) {
        int r = row0 + ty + i * 16;
        if (r >= M) continue;
#pragma unroll
        for (int j = 0; j < 8; j++) {
            int c = col0 + tx + j * 16;
            if (c >= Nd) continue;
            atomicAdd(&C[(long)r * Nd + c], acc[i][j]);
        }
    }
}

// ------- prep: zero stats; init dest with sum of per-type output biases -------
__global__ void k_prep(float* __restrict__ dest, const float* __restrict__ bb,
                       int co) {
    int i = blockIdx.x * blockDim.x + threadIdx.x;
    if (i < KT * 512) { d_cs[i] = 0.f; d_css[i] = 0.f; }
    if (i < NN * 256) {
        int c = i % co;
        dest[i] = bb[c] + bb[co + c] + bb[2 * co + c];
    }
}

__global__ void k_bnfinal(const float* __restrict__ gB,
                          const float* __restrict__ btB, int C) {
    int k = blockIdx.x;
    int c = threadIdx.x;
    if (c >= C) return;
    float mu  = d_cs[k * 512 + c] / (float)NN;
    float var = d_css[k * 512 + c] / (float)NN - mu * mu;
    var = fmaxf(var, 0.f);
    float s = gB[k * C + c] * rsqrtf(var + BN_EPS);
    d_scale[k * 512 + c] = s;
    d_shift[k * 512 + c] = btB[k * C + c] - mu * s;
}

__global__ void k_leaky() {
    int i = blockIdx.x * blockDim.x + threadIdx.x;
    if (i >= NN * 256) return;
    float v = d_accb[i];
    d_xcur[i] = (v > 0.f) ? v : 0.01f * v;
}

// ---------------- launch ----------------
extern "C" void kernel_launch(void* const* d_in, const int* in_sizes, int n_in,
                              void* d_out, int out_size) {
    // Resolve REAL device addresses of scratch passed by value (GB300 ATS
    // silently accepts host-shadow addresses otherwise!)
    float *p_acc, *p_xcur;
    cudaGetSymbolAddress((void**)&p_acc,  d_accb);
    cudaGetSymbolAddress((void**)&p_xcur, d_xcur);

    const float* x  = (const float*)d_in[0];
    const int*   ei = (const int*)d_in[1];
    const float* ea = (const float*)d_in[2];

    const int ciL[3] = {170, 256, 256};
    const int chL[3] = {340, 512, 512};
    const int co = 256;

    k_zero_counts<<<(KT * NN + 255) / 256, 256>>>();
    k_count<<<(KT * NE + 255) / 256, 256>>>(ei);
    k_scan<<<KT, 1024>>>();
    k_fill<<<(KT * NE + 255) / 256, 256>>>(ei);

    const float* xin = x;
    for (int l = 0; l < 3; l++) {
        int ci = ciL[l], ch = chL[l];
        const float* We = (const float*)d_in[3 + l * 8 + 0];
        const float* be = (const float*)d_in[3 + l * 8 + 1];
        const float* Wa = (const float*)d_in[3 + l * 8 + 2];
        const float* ba = (const float*)d_in[3 + l * 8 + 3];
        const float* g  = (const float*)d_in[3 + l * 8 + 4];
        const float* bt = (const float*)d_in[3 + l * 8 + 5];
        const float* Wb = (const float*)d_in[3 + l * 8 + 6];
        const float* bb = (const float*)d_in[3 + l * 8 + 7];
        float* dest = (l == 2) ? (float*)d_out : p_acc;

        dim3 ga(NN, KT);
        k_aggr<<<ga, 256>>>(xin, ei, ea, We, be, ci);

        k_prep<<<(NN * 256 + 255) / 256, 256>>>(dest, bb, co);

        dim3 g1((ch + BN - 1) / BN, (NN + BM - 1) / BM, KT);
        k_gemm1<<<g1, 256>>>(Wa, ba, NN, ci, ch);

        k_bnfinal<<<KT, 512>>>(g, bt, ch);

        dim3 g2((co + BN - 1) / BN, (NN + BM - 1) / BM, KT);
        k_gemm2<<<g2, 256>>>(Wb, dest, NN, ch, co);

        if (l < 2) {
            k_leaky<<<(NN * 256 + 255) / 256, 256>>>();
            xin = p_xcur;
        }
    }
}